// round 15
// baseline (speedup 1.0000x reference)
#include <cuda_runtime.h>
#include <cuda_fp16.h>

#define N_NODES 50000
#define N_EDGES 800000
#define IN_C    128
#define HID_C   64
#define OUT_C   64
#define GEMM_BLKS 391    // ceil(50000/128)
#define EDGE_BLKS 3125   // ceil(800000/256)
#define CONV_BLKS 1563   // ceil(800000/512), 2 edges/thread
#define SCAN_BLKS 196    // ceil(50000/256)
#define K4_BLKS   782    // ceil(50000/64)

// ---------------- scratch (static device globals; no allocations) ----------
// g_cnt: starts 0 (static init), CSR fill drains it back to 0 every run.
// g_bsum: reset by convert block 0; g_done: reset by k3 (between uses).
__device__ int g_src[N_EDGES];
__device__ int g_dst[N_EDGES];
__device__ int g_cnt[N_NODES];
__device__ int g_bsum[SCAN_BLKS];
__device__ int g_done = 0;
__device__ int g_rowptr[N_NODES + 1];
__device__ int g_col[N_EDGES];
__device__ __align__(16) float  g_dinv[N_NODES];
__device__ __align__(16) __half g_h1[N_NODES * HID_C];   // layer-1 h*dinv, fp16
__device__ __align__(16) __half g_h2[N_NODES * OUT_C];   // layer-2 h*dinv, fp16

// ---------------- packed f32x2 helpers (Blackwell FFMA2) -------------------
#define FMA2(d, a, b, c) \
    asm("fma.rn.f32x2 %0, %1, %2, %3;" : "=l"(d) : "l"(a), "l"(b), "l"(c))
#define PACK2(d, f) \
    asm("mov.b64 %0, {%1, %1};" : "=l"(d) : "r"(__float_as_uint(f)))
#define UNPACK2(lo, hi, p) \
    asm("mov.b64 {%0, %1}, %2;" : "=f"(lo), "=f"(hi) : "l"(p))

static __device__ __forceinline__ unsigned packh(float a, float b) {
    __half2 h = __floats2half2_rn(a, b);
    return *reinterpret_cast<unsigned*>(&h);
}

// ---------------- warp gather: sum of h rows over one node's edge list -----
static __device__ __forceinline__ float2 gather_node(const __half2* __restrict__ h2,
                                                     int gw, int lane) {
    float2 acc = __half22float2(h2[(size_t)gw * 32]);   // self term
    int e   = g_rowptr[gw];
    int end = g_rowptr[gw + 1];
    while (e < end) {
        int n = end - e;
        if (n > 32) n = 32;
        int idx = (lane < n) ? g_col[e + lane] : 0;     // coalesced batch load
        int j = 0;
        for (; j + 8 <= n; j += 8) {
            int s0 = __shfl_sync(0xffffffffu, idx, j + 0);
            int s1 = __shfl_sync(0xffffffffu, idx, j + 1);
            int s2 = __shfl_sync(0xffffffffu, idx, j + 2);
            int s3 = __shfl_sync(0xffffffffu, idx, j + 3);
            int s4 = __shfl_sync(0xffffffffu, idx, j + 4);
            int s5 = __shfl_sync(0xffffffffu, idx, j + 5);
            int s6 = __shfl_sync(0xffffffffu, idx, j + 6);
            int s7 = __shfl_sync(0xffffffffu, idx, j + 7);
            __half2 a0 = h2[(size_t)s0 * 32];           // 8 independent LDGs
            __half2 a1 = h2[(size_t)s1 * 32];
            __half2 a2 = h2[(size_t)s2 * 32];
            __half2 a3 = h2[(size_t)s3 * 32];
            __half2 a4 = h2[(size_t)s4 * 32];
            __half2 a5 = h2[(size_t)s5 * 32];
            __half2 a6 = h2[(size_t)s6 * 32];
            __half2 a7 = h2[(size_t)s7 * 32];
            float2 f0 = __half22float2(__hadd2(a0, a1));
            float2 f1 = __half22float2(__hadd2(a2, a3));
            float2 f2 = __half22float2(__hadd2(a4, a5));
            float2 f3 = __half22float2(__hadd2(a6, a7));
            acc.x += (f0.x + f1.x) + (f2.x + f3.x);
            acc.y += (f0.y + f1.y) + (f2.y + f3.y);
        }
        for (; j + 2 <= n; j += 2) {
            int s0 = __shfl_sync(0xffffffffu, idx, j);
            int s1 = __shfl_sync(0xffffffffu, idx, j + 1);
            __half2 a = h2[(size_t)s0 * 32];
            __half2 b = h2[(size_t)s1 * 32];
            float2 f = __half22float2(__hadd2(a, b));
            acc.x += f.x;
            acc.y += f.y;
        }
        if (j < n) {
            int s0 = __shfl_sync(0xffffffffu, idx, j);
            float2 f = __half22float2(h2[(size_t)s0 * 32]);
            acc.x += f.x;
            acc.y += f.y;
        }
        e += n;
    }
    return acc;
}

// ---------------- GEMM body: 128x64 tile, K-chunk 32, FFMA2 ---------------
template <int K>
__device__ __forceinline__ void gemm_body(const float* __restrict__ A,
                                          const float* __restrict__ W,
                                          __half* __restrict__ outh,
                                          float At[32][132], float Ws[32][68],
                                          int row0) {
    const int tid = threadIdx.x;
    const int tx  = tid & 15;       // 4 cols
    const int ty  = tid >> 4;       // 8 rows (4 row-pairs)

    unsigned long long acc[4][4];
    #pragma unroll
    for (int p = 0; p < 4; p++)
        #pragma unroll
        for (int c = 0; c < 4; c++) acc[p][c] = 0ULL;

    for (int kc = 0; kc < K; kc += 32) {
        if (kc) __syncthreads();
        #pragma unroll
        for (int l = 0; l < 2; l++) {                   // Ws: 32x64
            int j  = tid + l * 256;
            int k  = j >> 4;
            int c4 = (j & 15) << 2;
            *(float4*)&Ws[k][c4] = *(const float4*)(W + (size_t)(kc + k) * 64 + c4);
        }
        #pragma unroll
        for (int l = 0; l < 4; l++) {                   // At: transposed 128x32
            int j  = tid + l * 256;
            int r  = j >> 3;
            int k4 = (j & 7) << 2;
            float4 v = make_float4(0.f, 0.f, 0.f, 0.f);
            int row = row0 + r;
            if (row < N_NODES)
                v = *(const float4*)(A + (size_t)row * K + kc + k4);
            At[k4 + 0][r] = v.x;
            At[k4 + 1][r] = v.y;
            At[k4 + 2][r] = v.z;
            At[k4 + 3][r] = v.w;
        }
        __syncthreads();

        #pragma unroll 8
        for (int k = 0; k < 32; k++) {
            ulonglong2 a01 = *(const ulonglong2*)&At[k][ty * 8];
            ulonglong2 a23 = *(const ulonglong2*)&At[k][ty * 8 + 4];
            float4 b = *(const float4*)&Ws[k][tx * 4];
            unsigned long long B0, B1, B2, B3;
            PACK2(B0, b.x); PACK2(B1, b.y); PACK2(B2, b.z); PACK2(B3, b.w);
            FMA2(acc[0][0], a01.x, B0, acc[0][0]);
            FMA2(acc[0][1], a01.x, B1, acc[0][1]);
            FMA2(acc[0][2], a01.x, B2, acc[0][2]);
            FMA2(acc[0][3], a01.x, B3, acc[0][3]);
            FMA2(acc[1][0], a01.y, B0, acc[1][0]);
            FMA2(acc[1][1], a01.y, B1, acc[1][1]);
            FMA2(acc[1][2], a01.y, B2, acc[1][2]);
            FMA2(acc[1][3], a01.y, B3, acc[1][3]);
            FMA2(acc[2][0], a23.x, B0, acc[2][0]);
            FMA2(acc[2][1], a23.x, B1, acc[2][1]);
            FMA2(acc[2][2], a23.x, B2, acc[2][2]);
            FMA2(acc[2][3], a23.x, B3, acc[2][3]);
            FMA2(acc[3][0], a23.y, B0, acc[3][0]);
            FMA2(acc[3][1], a23.y, B1, acc[3][1]);
            FMA2(acc[3][2], a23.y, B2, acc[3][2]);
            FMA2(acc[3][3], a23.y, B3, acc[3][3]);
        }
    }

    #pragma unroll
    for (int p = 0; p < 4; p++) {
        float lo0, hi0, lo1, hi1, lo2, hi2, lo3, hi3;
        UNPACK2(lo0, hi0, acc[p][0]);
        UNPACK2(lo1, hi1, acc[p][1]);
        UNPACK2(lo2, hi2, acc[p][2]);
        UNPACK2(lo3, hi3, acc[p][3]);
        int r0 = row0 + ty * 8 + p * 2;
        if (r0 < N_NODES) {
            float s = g_dinv[r0];
            *(uint2*)(outh + (size_t)r0 * 64 + tx * 4) =
                make_uint2(packh(lo0 * s, lo1 * s), packh(lo2 * s, lo3 * s));
        }
        if (r0 + 1 < N_NODES) {
            float s = g_dinv[r0 + 1];
            *(uint2*)(outh + (size_t)(r0 + 1) * 64 + tx * 4) =
                make_uint2(packh(hi0 * s, hi1 * s), packh(hi2 * s, hi3 * s));
        }
    }
}

// ---------------- K1: fused [convert+count | scan] -------------------------
// Blocks [0, CONV_BLKS): convert 2 edges/thread + degree count, then signal.
// Blocks [CONV_BLKS, +SCAN_BLKS): spin until all counts final, then
// decoupled-lookback scan -> rowptr + dinv.
__global__ void k_conv_scan(const void* __restrict__ ei) {
    const int tid = threadIdx.x;
    if (blockIdx.x < CONV_BLKS) {
        __shared__ int s_nz;
        if (tid == 0) s_nz = 0;
        __syncthreads();
        if (tid < 128 && ((const int*)ei)[2 * tid + 1] != 0) atomicAdd(&s_nz, 1);
        __syncthreads();
        const bool is64 = (s_nz == 0);
        if (blockIdx.x == 0 && tid < SCAN_BLKS) g_bsum[tid] = 0;
        int p = blockIdx.x * 256 + tid;
        int i = p * 2;
        if (i < N_EDGES) {
            int s0, s1, d0, d1;
            if (is64) {
                longlong2 sp = ((const longlong2*)ei)[p];
                longlong2 dp = ((const longlong2*)((const long long*)ei + N_EDGES))[p];
                s0 = (int)sp.x; s1 = (int)sp.y;
                d0 = (int)dp.x; d1 = (int)dp.y;
            } else {
                int2 sp = ((const int2*)ei)[p];
                int2 dp = ((const int2*)((const int*)ei + N_EDGES))[p];
                s0 = sp.x; s1 = sp.y;
                d0 = dp.x; d1 = dp.y;
            }
            if ((unsigned)s0 >= N_NODES) s0 = 0;
            if ((unsigned)s1 >= N_NODES) s1 = 0;
            if ((unsigned)d0 >= N_NODES) d0 = 0;
            if ((unsigned)d1 >= N_NODES) d1 = 0;
            *(int2*)&g_src[i] = make_int2(s0, s1);
            *(int2*)&g_dst[i] = make_int2(d0, d1);
            atomicAdd(&g_cnt[d0], 1);
            atomicAdd(&g_cnt[d1], 1);
        }
        __threadfence();                 // counts + bsum reset visible
        __syncthreads();
        if (tid == 0) atomicAdd(&g_done, 1);
        return;
    }

    // ---- scan part ----
    const int b = blockIdx.x - CONV_BLKS;
    if (tid == 0) {                      // gate: all convert blocks finished
        while (*(volatile int*)&g_done < CONV_BLKS) __nanosleep(128);
    }
    __syncthreads();
    __threadfence();

    const int i = b * 256 + tid;
    int v = (i < N_NODES) ? g_cnt[i] : 0;
    const int lane = tid & 31, w = tid >> 5;
    __shared__ int wsum[8];
    __shared__ int s_total, s_prefix;

    int s = v;
    #pragma unroll
    for (int off = 1; off < 32; off <<= 1) {
        int n = __shfl_up_sync(0xffffffffu, s, off);
        if (lane >= off) s += n;
    }
    if (lane == 31) wsum[w] = s;
    __syncthreads();
    if (tid == 0) {
        int acc = 0;
        #pragma unroll
        for (int j = 0; j < 8; j++) { int t = wsum[j]; wsum[j] = acc; acc += t; }
        s_total = acc;
    }
    __syncthreads();
    int incl = wsum[w] + s;

    if (tid == 0) atomicExch(&g_bsum[b], s_total + 1);   // publish (self-flag)
    if (tid < 32) {
        int part = 0;
        for (int j = tid; j < b; j += 32) {
            int val;
            do { val = *(volatile int*)&g_bsum[j]; } while (val == 0);
            part += val - 1;
        }
        #pragma unroll
        for (int off = 16; off; off >>= 1)
            part += __shfl_down_sync(0xffffffffu, part, off);
        if (tid == 0) s_prefix = part;
    }
    __syncthreads();

    if (i < N_NODES) {
        g_rowptr[i + 1] = s_prefix + incl;
        g_dinv[i] = rsqrtf((float)(v + 1));
    }
    if (i == 0) g_rowptr[0] = 0;
}

// ---------------- K3: fused [GEMM1(*dinv) | CSR fill] (+g_done reset) ------
__global__ void k3_fused(const float* __restrict__ x,
                         const float* __restrict__ W1) {
    if (blockIdx.x < GEMM_BLKS) {
        __shared__ float At[32][132];
        __shared__ float Ws[32][68];
        gemm_body<IN_C>(x, W1, g_h1, At, Ws, blockIdx.x * 128);
    } else {
        if (blockIdx.x == GEMM_BLKS && threadIdx.x == 0) g_done = 0;  // reset
        int i = (blockIdx.x - GEMM_BLKS) * 256 + threadIdx.x;
        if (i < N_EDGES) {
            int d = g_dst[i];
            int r = atomicSub(&g_cnt[d], 1);   // drains g_cnt back to 0
            int pos = g_rowptr[d] + r - 1;
            if ((unsigned)pos < N_EDGES) g_col[pos] = g_src[i];
        }
    }
}

// ---------------- K4: fused [aggregate L1 + bias + ReLU + GEMM2*dinv] ------
// Block owns 64 nodes (R12 shape). Phase A uses a DYNAMIC shared cursor so
// early-finishing warps steal the next node (intra-block load balancing).
__global__ void k4_agg_gemm(const float* __restrict__ b1,
                            const float* __restrict__ W2) {
    __shared__ float z1t[64][68];   // [k][row], fp32, pad 68
    __shared__ float Ws[64][68];    // [k][col], fp32
    __shared__ int   cursor;

    const int tid   = threadIdx.x;
    const int node0 = blockIdx.x * 64;
    const int lane  = tid & 31;

    if (tid == 0) cursor = 0;

    // stage W2 (64x64)
    #pragma unroll
    for (int l = 0; l < 4; l++) {
        int j  = tid + l * 256;
        int k  = j >> 4;
        int c4 = (j & 15) << 2;
        *(float4*)&Ws[k][c4] = *(const float4*)(W2 + (size_t)k * 64 + c4);
    }
    __syncthreads();                 // cursor + Ws visible

    // Phase A: aggregate 64 nodes, dynamic warp scheduling
    const __half2* h2 = (const __half2*)g_h1 + lane;
    float2 bb = ((const float2*)b1)[lane];
    for (;;) {
        int r;
        if (lane == 0) r = atomicAdd(&cursor, 1);
        r = __shfl_sync(0xffffffffu, r, 0);
        if (r >= 64) break;
        int gw = node0 + r;
        float2 v = make_float2(0.0f, 0.0f);
        if (gw < N_NODES) {
            float2 acc = gather_node(h2, gw, lane);
            float dvd = g_dinv[gw];
            v.x = fmaxf(fmaf(acc.x, dvd, bb.x), 0.0f);
            v.y = fmaxf(fmaf(acc.y, dvd, bb.y), 0.0f);
        }
        z1t[2 * lane + 0][r] = v.x;  // transposed store
        z1t[2 * lane + 1][r] = v.y;
    }
    __syncthreads();

    // Phase B: GEMM 64x64x64 from smem, FFMA2 row-pairs
    const int tx = tid & 15;         // 4 cols
    const int ty = tid >> 4;         // 4 rows (2 pairs)
    unsigned long long acc[2][4];
    #pragma unroll
    for (int p = 0; p < 2; p++)
        #pragma unroll
        for (int c = 0; c < 4; c++) acc[p][c] = 0ULL;

    #pragma unroll 8
    for (int k = 0; k < 64; k++) {
        ulonglong2 a = *(const ulonglong2*)&z1t[k][ty * 4];
        float4 b = *(const float4*)&Ws[k][tx * 4];
        unsigned long long B0, B1, B2, B3;
        PACK2(B0, b.x); PACK2(B1, b.y); PACK2(B2, b.z); PACK2(B3, b.w);
        FMA2(acc[0][0], a.x, B0, acc[0][0]);
        FMA2(acc[0][1], a.x, B1, acc[0][1]);
        FMA2(acc[0][2], a.x, B2, acc[0][2]);
        FMA2(acc[0][3], a.x, B3, acc[0][3]);
        FMA2(acc[1][0], a.y, B0, acc[1][0]);
        FMA2(acc[1][1], a.y, B1, acc[1][1]);
        FMA2(acc[1][2], a.y, B2, acc[1][2]);
        FMA2(acc[1][3], a.y, B3, acc[1][3]);
    }

    #pragma unroll
    for (int p = 0; p < 2; p++) {
        float lo0, hi0, lo1, hi1, lo2, hi2, lo3, hi3;
        UNPACK2(lo0, hi0, acc[p][0]);
        UNPACK2(lo1, hi1, acc[p][1]);
        UNPACK2(lo2, hi2, acc[p][2]);
        UNPACK2(lo3, hi3, acc[p][3]);
        int r0 = node0 + ty * 4 + p * 2;
        if (r0 < N_NODES) {
            float s = g_dinv[r0];
            *(uint2*)(g_h2 + (size_t)r0 * 64 + tx * 4) =
                make_uint2(packh(lo0 * s, lo1 * s), packh(lo2 * s, lo3 * s));
        }
        if (r0 + 1 < N_NODES) {
            float s = g_dinv[r0 + 1];
            *(uint2*)(g_h2 + (size_t)(r0 + 1) * 64 + tx * 4) =
                make_uint2(packh(hi0 * s, hi1 * s), packh(hi2 * s, hi3 * s));
        }
    }
}

// ---------------- K5: final aggregation (layer 2) ---------------------------
__global__ void k_aggregate2(const float* __restrict__ bias,
                             float* __restrict__ outp) {
    int gw   = (blockIdx.x * blockDim.x + threadIdx.x) >> 5;
    int lane = threadIdx.x & 31;
    if (gw >= N_NODES) return;

    const __half2* h2 = (const __half2*)g_h2 + lane;
    float2 acc = gather_node(h2, gw, lane);

    float  dvd = g_dinv[gw];
    float2 bb  = ((const float2*)bias)[lane];
    float ox = fmaf(acc.x, dvd, bb.x);
    float oy = fmaf(acc.y, dvd, bb.y);
    ((float2*)outp)[(size_t)gw * 32 + lane] = make_float2(ox, oy);
}

// ---------------- launch ---------------------------------------------------
extern "C" void kernel_launch(void* const* d_in, const int* in_sizes, int n_in,
                              void* d_out, int out_size) {
    const float* x  = (const float*)d_in[0];
    const void*  ei = d_in[1];                 // int32 OR int64 [2, 800000]
    const float* W1 = (const float*)d_in[2];
    const float* b1 = (const float*)d_in[3];
    const float* W2 = (const float*)d_in[4];
    const float* b2 = (const float*)d_in[5];
    float*      out = (float*)d_out;

    const int TB = 256;
    const int aggBlocks = (N_NODES * 32 + TB - 1) / TB;   // 6250

    k_conv_scan<<<CONV_BLKS + SCAN_BLKS, TB>>>(ei);       // convert+count -> scan
    k3_fused<<<GEMM_BLKS + EDGE_BLKS, TB>>>(x, W1);       // GEMM1*dinv || CSR fill
    k4_agg_gemm<<<K4_BLKS, TB>>>(b1, W2);                 // agg1+ReLU+GEMM2 -> g_h2
    k_aggregate2<<<aggBlocks, TB>>>(b2, out);             // -> out
}

// round 16
// speedup vs baseline: 1.0422x; 1.0422x over previous
#include <cuda_runtime.h>
#include <cuda_fp16.h>

#define N_NODES 50000
#define N_EDGES 800000
#define IN_C    128
#define HID_C   64
#define OUT_C   64
#define GEMM_BLKS 391    // ceil(50000/128)
#define EDGE_BLKS 3125   // ceil(800000/256)
#define CONV_BLKS 1563   // ceil(800000/512), 2 edges/thread
#define SCAN_BLKS 196    // ceil(50000/256)
#define K4_BLKS   3125   // ceil(50000/16), 16 nodes/block, 1 node/warp

// ---------------- scratch (static device globals; no allocations) ----------
// g_cnt: starts 0 (static init), CSR fill drains it back to 0 every run.
// g_bsum: reset to 0 inside k_convert_count every run.
__device__ int g_src[N_EDGES];
__device__ int g_dst[N_EDGES];
__device__ int g_cnt[N_NODES];
__device__ int g_bsum[SCAN_BLKS];
__device__ int g_rowptr[N_NODES + 1];
__device__ int g_col[N_EDGES];
__device__ __align__(16) float  g_dinv[N_NODES];
__device__ __align__(16) __half g_h1[N_NODES * HID_C];   // layer-1 h*dinv, fp16
__device__ __align__(16) __half g_h2[N_NODES * OUT_C];   // layer-2 h*dinv, fp16

// ---------------- packed f32x2 helpers (Blackwell FFMA2) -------------------
#define FMA2(d, a, b, c) \
    asm("fma.rn.f32x2 %0, %1, %2, %3;" : "=l"(d) : "l"(a), "l"(b), "l"(c))
#define PACK2(d, f) \
    asm("mov.b64 %0, {%1, %1};" : "=l"(d) : "r"(__float_as_uint(f)))
#define UNPACK2(lo, hi, p) \
    asm("mov.b64 {%0, %1}, %2;" : "=f"(lo), "=f"(hi) : "l"(p))

static __device__ __forceinline__ unsigned packh(float a, float b) {
    __half2 h = __floats2half2_rn(a, b);
    return *reinterpret_cast<unsigned*>(&h);
}

// ---------------- warp gather: sum of h rows over one node's edge list -----
static __device__ __forceinline__ float2 gather_node(const __half2* __restrict__ h2,
                                                     int gw, int lane) {
    float2 acc = __half22float2(h2[(size_t)gw * 32]);   // self term
    int e   = g_rowptr[gw];
    int end = g_rowptr[gw + 1];
    while (e < end) {
        int n = end - e;
        if (n > 32) n = 32;
        int idx = (lane < n) ? g_col[e + lane] : 0;     // coalesced batch load
        int j = 0;
        for (; j + 8 <= n; j += 8) {
            int s0 = __shfl_sync(0xffffffffu, idx, j + 0);
            int s1 = __shfl_sync(0xffffffffu, idx, j + 1);
            int s2 = __shfl_sync(0xffffffffu, idx, j + 2);
            int s3 = __shfl_sync(0xffffffffu, idx, j + 3);
            int s4 = __shfl_sync(0xffffffffu, idx, j + 4);
            int s5 = __shfl_sync(0xffffffffu, idx, j + 5);
            int s6 = __shfl_sync(0xffffffffu, idx, j + 6);
            int s7 = __shfl_sync(0xffffffffu, idx, j + 7);
            __half2 a0 = h2[(size_t)s0 * 32];           // 8 independent LDGs
            __half2 a1 = h2[(size_t)s1 * 32];
            __half2 a2 = h2[(size_t)s2 * 32];
            __half2 a3 = h2[(size_t)s3 * 32];
            __half2 a4 = h2[(size_t)s4 * 32];
            __half2 a5 = h2[(size_t)s5 * 32];
            __half2 a6 = h2[(size_t)s6 * 32];
            __half2 a7 = h2[(size_t)s7 * 32];
            float2 f0 = __half22float2(__hadd2(a0, a1));
            float2 f1 = __half22float2(__hadd2(a2, a3));
            float2 f2 = __half22float2(__hadd2(a4, a5));
            float2 f3 = __half22float2(__hadd2(a6, a7));
            acc.x += (f0.x + f1.x) + (f2.x + f3.x);
            acc.y += (f0.y + f1.y) + (f2.y + f3.y);
        }
        for (; j + 2 <= n; j += 2) {
            int s0 = __shfl_sync(0xffffffffu, idx, j);
            int s1 = __shfl_sync(0xffffffffu, idx, j + 1);
            __half2 a = h2[(size_t)s0 * 32];
            __half2 b = h2[(size_t)s1 * 32];
            float2 f = __half22float2(__hadd2(a, b));
            acc.x += f.x;
            acc.y += f.y;
        }
        if (j < n) {
            int s0 = __shfl_sync(0xffffffffu, idx, j);
            float2 f = __half22float2(h2[(size_t)s0 * 32]);
            acc.x += f.x;
            acc.y += f.y;
        }
        e += n;
    }
    return acc;
}

// ---------------- GEMM body: 128x64 tile, K-chunk 32, FFMA2 ---------------
template <int K>
__device__ __forceinline__ void gemm_body(const float* __restrict__ A,
                                          const float* __restrict__ W,
                                          __half* __restrict__ outh,
                                          float At[32][132], float Ws[32][68],
                                          int row0) {
    const int tid = threadIdx.x;
    const int tx  = tid & 15;       // 4 cols
    const int ty  = tid >> 4;       // 8 rows (4 row-pairs)

    unsigned long long acc[4][4];
    #pragma unroll
    for (int p = 0; p < 4; p++)
        #pragma unroll
        for (int c = 0; c < 4; c++) acc[p][c] = 0ULL;

    for (int kc = 0; kc < K; kc += 32) {
        if (kc) __syncthreads();
        #pragma unroll
        for (int l = 0; l < 2; l++) {                   // Ws: 32x64
            int j  = tid + l * 256;
            int k  = j >> 4;
            int c4 = (j & 15) << 2;
            *(float4*)&Ws[k][c4] = *(const float4*)(W + (size_t)(kc + k) * 64 + c4);
        }
        #pragma unroll
        for (int l = 0; l < 4; l++) {                   // At: transposed 128x32
            int j  = tid + l * 256;
            int r  = j >> 3;
            int k4 = (j & 7) << 2;
            float4 v = make_float4(0.f, 0.f, 0.f, 0.f);
            int row = row0 + r;
            if (row < N_NODES)
                v = *(const float4*)(A + (size_t)row * K + kc + k4);
            At[k4 + 0][r] = v.x;
            At[k4 + 1][r] = v.y;
            At[k4 + 2][r] = v.z;
            At[k4 + 3][r] = v.w;
        }
        __syncthreads();

        #pragma unroll 8
        for (int k = 0; k < 32; k++) {
            ulonglong2 a01 = *(const ulonglong2*)&At[k][ty * 8];
            ulonglong2 a23 = *(const ulonglong2*)&At[k][ty * 8 + 4];
            float4 b = *(const float4*)&Ws[k][tx * 4];
            unsigned long long B0, B1, B2, B3;
            PACK2(B0, b.x); PACK2(B1, b.y); PACK2(B2, b.z); PACK2(B3, b.w);
            FMA2(acc[0][0], a01.x, B0, acc[0][0]);
            FMA2(acc[0][1], a01.x, B1, acc[0][1]);
            FMA2(acc[0][2], a01.x, B2, acc[0][2]);
            FMA2(acc[0][3], a01.x, B3, acc[0][3]);
            FMA2(acc[1][0], a01.y, B0, acc[1][0]);
            FMA2(acc[1][1], a01.y, B1, acc[1][1]);
            FMA2(acc[1][2], a01.y, B2, acc[1][2]);
            FMA2(acc[1][3], a01.y, B3, acc[1][3]);
            FMA2(acc[2][0], a23.x, B0, acc[2][0]);
            FMA2(acc[2][1], a23.x, B1, acc[2][1]);
            FMA2(acc[2][2], a23.x, B2, acc[2][2]);
            FMA2(acc[2][3], a23.x, B3, acc[2][3]);
            FMA2(acc[3][0], a23.y, B0, acc[3][0]);
            FMA2(acc[3][1], a23.y, B1, acc[3][1]);
            FMA2(acc[3][2], a23.y, B2, acc[3][2]);
            FMA2(acc[3][3], a23.y, B3, acc[3][3]);
        }
    }

    #pragma unroll
    for (int p = 0; p < 4; p++) {
        float lo0, hi0, lo1, hi1, lo2, hi2, lo3, hi3;
        UNPACK2(lo0, hi0, acc[p][0]);
        UNPACK2(lo1, hi1, acc[p][1]);
        UNPACK2(lo2, hi2, acc[p][2]);
        UNPACK2(lo3, hi3, acc[p][3]);
        int r0 = row0 + ty * 8 + p * 2;
        if (r0 < N_NODES) {
            float s = g_dinv[r0];
            *(uint2*)(outh + (size_t)r0 * 64 + tx * 4) =
                make_uint2(packh(lo0 * s, lo1 * s), packh(lo2 * s, lo3 * s));
        }
        if (r0 + 1 < N_NODES) {
            float s = g_dinv[r0 + 1];
            *(uint2*)(outh + (size_t)(r0 + 1) * 64 + tx * 4) =
                make_uint2(packh(hi0 * s, hi1 * s), packh(hi2 * s, hi3 * s));
        }
    }
}

// ---------------- K1: convert + degree count, 2 edges/thread ---------------
__global__ void k_convert_count(const void* __restrict__ ei) {
    __shared__ int s_nz;
    const int tid = threadIdx.x;
    if (tid == 0) s_nz = 0;
    __syncthreads();
    if (tid < 128 && ((const int*)ei)[2 * tid + 1] != 0) atomicAdd(&s_nz, 1);
    __syncthreads();
    const bool is64 = (s_nz == 0);
    if (blockIdx.x == 0 && tid < SCAN_BLKS) g_bsum[tid] = 0;
    int p = blockIdx.x * 256 + tid;
    int i = p * 2;
    if (i < N_EDGES) {
        int s0, s1, d0, d1;
        if (is64) {
            longlong2 sp = ((const longlong2*)ei)[p];
            longlong2 dp = ((const longlong2*)((const long long*)ei + N_EDGES))[p];
            s0 = (int)sp.x; s1 = (int)sp.y;
            d0 = (int)dp.x; d1 = (int)dp.y;
        } else {
            int2 sp = ((const int2*)ei)[p];
            int2 dp = ((const int2*)((const int*)ei + N_EDGES))[p];
            s0 = sp.x; s1 = sp.y;
            d0 = dp.x; d1 = dp.y;
        }
        if ((unsigned)s0 >= N_NODES) s0 = 0;
        if ((unsigned)s1 >= N_NODES) s1 = 0;
        if ((unsigned)d0 >= N_NODES) d0 = 0;
        if ((unsigned)d1 >= N_NODES) d1 = 0;
        *(int2*)&g_src[i] = make_int2(s0, s1);
        *(int2*)&g_dst[i] = make_int2(d0, d1);
        atomicAdd(&g_cnt[d0], 1);
        atomicAdd(&g_cnt[d1], 1);
    }
}

// ---------------- K2: single-kernel decoupled-lookback scan ----------------
__global__ void k_scan() {
    const int b = blockIdx.x, tid = threadIdx.x;
    const int i = b * 256 + tid;
    int v = (i < N_NODES) ? g_cnt[i] : 0;
    const int lane = tid & 31, w = tid >> 5;
    __shared__ int wsum[8];
    __shared__ int s_total, s_prefix;

    int s = v;
    #pragma unroll
    for (int off = 1; off < 32; off <<= 1) {
        int n = __shfl_up_sync(0xffffffffu, s, off);
        if (lane >= off) s += n;
    }
    if (lane == 31) wsum[w] = s;
    __syncthreads();
    if (tid == 0) {
        int acc = 0;
        #pragma unroll
        for (int j = 0; j < 8; j++) { int t = wsum[j]; wsum[j] = acc; acc += t; }
        s_total = acc;
    }
    __syncthreads();
    int incl = wsum[w] + s;

    if (tid == 0) atomicExch(&g_bsum[b], s_total + 1);
    if (tid < 32) {
        int part = 0;
        for (int j = tid; j < b; j += 32) {
            int val;
            do { val = *(volatile int*)&g_bsum[j]; } while (val == 0);
            part += val - 1;
        }
        #pragma unroll
        for (int off = 16; off; off >>= 1)
            part += __shfl_down_sync(0xffffffffu, part, off);
        if (tid == 0) s_prefix = part;
    }
    __syncthreads();

    if (i < N_NODES) {
        g_rowptr[i + 1] = s_prefix + incl;
        g_dinv[i] = rsqrtf((float)(v + 1));
    }
    if (i == 0) g_rowptr[0] = 0;
}

// ---------------- K3: fused [GEMM1(*dinv) | CSR fill] ----------------------
__global__ void k3_fused(const float* __restrict__ x,
                         const float* __restrict__ W1) {
    if (blockIdx.x < GEMM_BLKS) {
        __shared__ float At[32][132];
        __shared__ float Ws[32][68];
        gemm_body<IN_C>(x, W1, g_h1, At, Ws, blockIdx.x * 128);
    } else {
        int i = (blockIdx.x - GEMM_BLKS) * 256 + threadIdx.x;
        if (i < N_EDGES) {
            int d = g_dst[i];
            int r = atomicSub(&g_cnt[d], 1);   // drains g_cnt back to 0
            int pos = g_rowptr[d] + r - 1;
            if ((unsigned)pos < N_EDGES) g_col[pos] = g_src[i];
        }
    }
}

// ---------------- K4: fused [aggregate L1 + bias + ReLU + GEMM2*dinv] ------
// 512 threads, 16 nodes/block, ONE NODE PER WARP (restores 50k-warp
// parallelism the 64-node tile destroyed). Grid 3125 -> 21 blocks/SM queued.
// Phase B: 16x64x64 FFMA2 GEMM on threads 0..127 from smem.
__global__ void k4_agg_gemm(const float* __restrict__ b1,
                            const float* __restrict__ W2) {
    __shared__ float z1t[64][20];   // [k][row], 16 rows + pad (80B stride)
    __shared__ float Ws[64][68];    // [k][col], fp32

    const int tid   = threadIdx.x;
    const int node0 = blockIdx.x * 16;
    const int lane  = tid & 31;
    const int w     = tid >> 5;     // 0..15: one node per warp

    // stage W2 (64x64): 512 threads x 2 float4
    #pragma unroll
    for (int l = 0; l < 2; l++) {
        int j  = tid + l * 512;
        int k  = j >> 4;
        int c4 = (j & 15) << 2;
        *(float4*)&Ws[k][c4] = *(const float4*)(W2 + (size_t)k * 64 + c4);
    }

    // Phase A: each warp aggregates exactly one node
    const __half2* h2 = (const __half2*)g_h1 + lane;
    float2 bb = ((const float2*)b1)[lane];
    {
        int gw = node0 + w;
        float2 v = make_float2(0.0f, 0.0f);
        if (gw < N_NODES) {
            float2 acc = gather_node(h2, gw, lane);
            float dvd = g_dinv[gw];
            v.x = fmaxf(fmaf(acc.x, dvd, bb.x), 0.0f);
            v.y = fmaxf(fmaf(acc.y, dvd, bb.y), 0.0f);
        }
        z1t[2 * lane + 0][w] = v.x;  // transposed store
        z1t[2 * lane + 1][w] = v.y;
    }
    __syncthreads();

    // Phase B: GEMM 16x64x64 from smem on threads 0..127
    if (tid < 128) {
        const int tx = tid & 15;     // cols tx*4..tx*4+3
        const int ty = tid >> 4;     // row-pair 0..7 (16 rows)
        unsigned long long acc[4];
        #pragma unroll
        for (int c = 0; c < 4; c++) acc[c] = 0ULL;

        #pragma unroll 16
        for (int k = 0; k < 64; k++) {
            unsigned long long a = *(const unsigned long long*)&z1t[k][ty * 2];
            float4 b = *(const float4*)&Ws[k][tx * 4];
            unsigned long long B0, B1, B2, B3;
            PACK2(B0, b.x); PACK2(B1, b.y); PACK2(B2, b.z); PACK2(B3, b.w);
            FMA2(acc[0], a, B0, acc[0]);
            FMA2(acc[1], a, B1, acc[1]);
            FMA2(acc[2], a, B2, acc[2]);
            FMA2(acc[3], a, B3, acc[3]);
        }

        float lo0, hi0, lo1, hi1, lo2, hi2, lo3, hi3;
        UNPACK2(lo0, hi0, acc[0]);
        UNPACK2(lo1, hi1, acc[1]);
        UNPACK2(lo2, hi2, acc[2]);
        UNPACK2(lo3, hi3, acc[3]);
        int r0 = node0 + ty * 2;
        if (r0 < N_NODES) {
            float s = g_dinv[r0];
            *(uint2*)(g_h2 + (size_t)r0 * 64 + tx * 4) =
                make_uint2(packh(lo0 * s, lo1 * s), packh(lo2 * s, lo3 * s));
        }
        if (r0 + 1 < N_NODES) {
            float s = g_dinv[r0 + 1];
            *(uint2*)(g_h2 + (size_t)(r0 + 1) * 64 + tx * 4) =
                make_uint2(packh(hi0 * s, hi1 * s), packh(hi2 * s, hi3 * s));
        }
    }
}

// ---------------- K5: final aggregation (layer 2) ---------------------------
__global__ void k_aggregate2(const float* __restrict__ bias,
                             float* __restrict__ outp) {
    int gw   = (blockIdx.x * blockDim.x + threadIdx.x) >> 5;
    int lane = threadIdx.x & 31;
    if (gw >= N_NODES) return;

    const __half2* h2 = (const __half2*)g_h2 + lane;
    float2 acc = gather_node(h2, gw, lane);

    float  dvd = g_dinv[gw];
    float2 bb  = ((const float2*)bias)[lane];
    float ox = fmaf(acc.x, dvd, bb.x);
    float oy = fmaf(acc.y, dvd, bb.y);
    ((float2*)outp)[(size_t)gw * 32 + lane] = make_float2(ox, oy);
}

// ---------------- launch ---------------------------------------------------
extern "C" void kernel_launch(void* const* d_in, const int* in_sizes, int n_in,
                              void* d_out, int out_size) {
    const float* x  = (const float*)d_in[0];
    const void*  ei = d_in[1];                 // int32 OR int64 [2, 800000]
    const float* W1 = (const float*)d_in[2];
    const float* b1 = (const float*)d_in[3];
    const float* W2 = (const float*)d_in[4];
    const float* b2 = (const float*)d_in[5];
    float*      out = (float*)d_out;

    const int TB = 256;
    const int aggBlocks = (N_NODES * 32 + TB - 1) / TB;   // 6250

    k_convert_count<<<CONV_BLKS, TB>>>(ei);               // edges -> src/dst/cnt
    k_scan<<<SCAN_BLKS, TB>>>();                          // rowptr + dinv
    k3_fused<<<GEMM_BLKS + EDGE_BLKS, TB>>>(x, W1);       // GEMM1*dinv || CSR fill
    k4_agg_gemm<<<K4_BLKS, 512>>>(b1, W2);                // agg1+ReLU+GEMM2 -> g_h2
    k_aggregate2<<<aggBlocks, TB>>>(b2, out);             // -> out
}

// round 17
// speedup vs baseline: 1.1125x; 1.0674x over previous
#include <cuda_runtime.h>
#include <cuda_fp16.h>

#define N_NODES 50000
#define N_EDGES 800000
#define IN_C    128
#define HID_C   64
#define OUT_C   64
#define GEMM_BLKS 391    // ceil(50000/128)
#define EDGE_BLKS 3125   // ceil(800000/256)
#define CONV_BLKS 1563   // ceil(800000/512), 2 edges/thread
#define SCAN_BLKS 196    // ceil(50000/256)
#define K4_BLKS   782    // ceil(50000/64)

// ---------------- scratch (static device globals; no allocations) ----------
// g_cnt: starts 0 (static init), CSR fill drains it back to 0 every run.
// g_bsum: reset to 0 inside k_convert_count every run.
__device__ int g_src[N_EDGES];
__device__ int g_dst[N_EDGES];
__device__ int g_cnt[N_NODES];
__device__ int g_bsum[SCAN_BLKS];
__device__ int g_rowptr[N_NODES + 1];
__device__ int g_col[N_EDGES];
__device__ __align__(16) float  g_dinv[N_NODES];
__device__ __align__(16) __half g_h1[N_NODES * HID_C];   // layer-1 h*dinv, fp16
__device__ __align__(16) __half g_h2[N_NODES * OUT_C];   // layer-2 h*dinv, fp16

// ---------------- packed f32x2 helpers (Blackwell FFMA2) -------------------
#define FMA2(d, a, b, c) \
    asm("fma.rn.f32x2 %0, %1, %2, %3;" : "=l"(d) : "l"(a), "l"(b), "l"(c))
#define PACK2(d, f) \
    asm("mov.b64 %0, {%1, %1};" : "=l"(d) : "r"(__float_as_uint(f)))
#define UNPACK2(lo, hi, p) \
    asm("mov.b64 {%0, %1}, %2;" : "=f"(lo), "=f"(hi) : "l"(p))

static __device__ __forceinline__ unsigned packh(float a, float b) {
    __half2 h = __floats2half2_rn(a, b);
    return *reinterpret_cast<unsigned*>(&h);
}

// ---------------- warp gather: sum of h rows over one node's edge list -----
static __device__ __forceinline__ float2 gather_node(const __half2* __restrict__ h2,
                                                     int gw, int lane) {
    float2 acc = __half22float2(h2[(size_t)gw * 32]);   // self term
    int e   = g_rowptr[gw];
    int end = g_rowptr[gw + 1];
    while (e < end) {
        int n = end - e;
        if (n > 32) n = 32;
        int idx = (lane < n) ? g_col[e + lane] : 0;     // coalesced batch load
        int j = 0;
        for (; j + 8 <= n; j += 8) {
            int s0 = __shfl_sync(0xffffffffu, idx, j + 0);
            int s1 = __shfl_sync(0xffffffffu, idx, j + 1);
            int s2 = __shfl_sync(0xffffffffu, idx, j + 2);
            int s3 = __shfl_sync(0xffffffffu, idx, j + 3);
            int s4 = __shfl_sync(0xffffffffu, idx, j + 4);
            int s5 = __shfl_sync(0xffffffffu, idx, j + 5);
            int s6 = __shfl_sync(0xffffffffu, idx, j + 6);
            int s7 = __shfl_sync(0xffffffffu, idx, j + 7);
            __half2 a0 = h2[(size_t)s0 * 32];           // 8 independent LDGs
            __half2 a1 = h2[(size_t)s1 * 32];
            __half2 a2 = h2[(size_t)s2 * 32];
            __half2 a3 = h2[(size_t)s3 * 32];
            __half2 a4 = h2[(size_t)s4 * 32];
            __half2 a5 = h2[(size_t)s5 * 32];
            __half2 a6 = h2[(size_t)s6 * 32];
            __half2 a7 = h2[(size_t)s7 * 32];
            float2 f0 = __half22float2(__hadd2(a0, a1));
            float2 f1 = __half22float2(__hadd2(a2, a3));
            float2 f2 = __half22float2(__hadd2(a4, a5));
            float2 f3 = __half22float2(__hadd2(a6, a7));
            acc.x += (f0.x + f1.x) + (f2.x + f3.x);
            acc.y += (f0.y + f1.y) + (f2.y + f3.y);
        }
        for (; j + 2 <= n; j += 2) {
            int s0 = __shfl_sync(0xffffffffu, idx, j);
            int s1 = __shfl_sync(0xffffffffu, idx, j + 1);
            __half2 a = h2[(size_t)s0 * 32];
            __half2 b = h2[(size_t)s1 * 32];
            float2 f = __half22float2(__hadd2(a, b));
            acc.x += f.x;
            acc.y += f.y;
        }
        if (j < n) {
            int s0 = __shfl_sync(0xffffffffu, idx, j);
            float2 f = __half22float2(h2[(size_t)s0 * 32]);
            acc.x += f.x;
            acc.y += f.y;
        }
        e += n;
    }
    return acc;
}

// ---------------- GEMM body: 128x64 tile, K-chunk 32, FFMA2 ---------------
// PDL: mainloop reads only harness inputs (A=x, W) — runs pre-sync; the
// cudaGridDependencySynchronize() sits just before the g_dinv epilogue.
template <int K>
__device__ __forceinline__ void gemm_body(const float* __restrict__ A,
                                          const float* __restrict__ W,
                                          __half* __restrict__ outh,
                                          float At[32][132], float Ws[32][68],
                                          int row0) {
    const int tid = threadIdx.x;
    const int tx  = tid & 15;       // 4 cols
    const int ty  = tid >> 4;       // 8 rows (4 row-pairs)

    unsigned long long acc[4][4];
    #pragma unroll
    for (int p = 0; p < 4; p++)
        #pragma unroll
        for (int c = 0; c < 4; c++) acc[p][c] = 0ULL;

    for (int kc = 0; kc < K; kc += 32) {
        if (kc) __syncthreads();
        #pragma unroll
        for (int l = 0; l < 2; l++) {                   // Ws: 32x64
            int j  = tid + l * 256;
            int k  = j >> 4;
            int c4 = (j & 15) << 2;
            *(float4*)&Ws[k][c4] = *(const float4*)(W + (size_t)(kc + k) * 64 + c4);
        }
        #pragma unroll
        for (int l = 0; l < 4; l++) {                   // At: transposed 128x32
            int j  = tid + l * 256;
            int r  = j >> 3;
            int k4 = (j & 7) << 2;
            float4 v = make_float4(0.f, 0.f, 0.f, 0.f);
            int row = row0 + r;
            if (row < N_NODES)
                v = *(const float4*)(A + (size_t)row * K + kc + k4);
            At[k4 + 0][r] = v.x;
            At[k4 + 1][r] = v.y;
            At[k4 + 2][r] = v.z;
            At[k4 + 3][r] = v.w;
        }
        __syncthreads();

        #pragma unroll 8
        for (int k = 0; k < 32; k++) {
            ulonglong2 a01 = *(const ulonglong2*)&At[k][ty * 8];
            ulonglong2 a23 = *(const ulonglong2*)&At[k][ty * 8 + 4];
            float4 b = *(const float4*)&Ws[k][tx * 4];
            unsigned long long B0, B1, B2, B3;
            PACK2(B0, b.x); PACK2(B1, b.y); PACK2(B2, b.z); PACK2(B3, b.w);
            FMA2(acc[0][0], a01.x, B0, acc[0][0]);
            FMA2(acc[0][1], a01.x, B1, acc[0][1]);
            FMA2(acc[0][2], a01.x, B2, acc[0][2]);
            FMA2(acc[0][3], a01.x, B3, acc[0][3]);
            FMA2(acc[1][0], a01.y, B0, acc[1][0]);
            FMA2(acc[1][1], a01.y, B1, acc[1][1]);
            FMA2(acc[1][2], a01.y, B2, acc[1][2]);
            FMA2(acc[1][3], a01.y, B3, acc[1][3]);
            FMA2(acc[2][0], a23.x, B0, acc[2][0]);
            FMA2(acc[2][1], a23.x, B1, acc[2][1]);
            FMA2(acc[2][2], a23.x, B2, acc[2][2]);
            FMA2(acc[2][3], a23.x, B3, acc[2][3]);
            FMA2(acc[3][0], a23.y, B0, acc[3][0]);
            FMA2(acc[3][1], a23.y, B1, acc[3][1]);
            FMA2(acc[3][2], a23.y, B2, acc[3][2]);
            FMA2(acc[3][3], a23.y, B3, acc[3][3]);
        }
    }

    cudaGridDependencySynchronize();     // need g_dinv (scan output) from here

    #pragma unroll
    for (int p = 0; p < 4; p++) {
        float lo0, hi0, lo1, hi1, lo2, hi2, lo3, hi3;
        UNPACK2(lo0, hi0, acc[p][0]);
        UNPACK2(lo1, hi1, acc[p][1]);
        UNPACK2(lo2, hi2, acc[p][2]);
        UNPACK2(lo3, hi3, acc[p][3]);
        int r0 = row0 + ty * 8 + p * 2;
        if (r0 < N_NODES) {
            float s = g_dinv[r0];
            *(uint2*)(outh + (size_t)r0 * 64 + tx * 4) =
                make_uint2(packh(lo0 * s, lo1 * s), packh(lo2 * s, lo3 * s));
        }
        if (r0 + 1 < N_NODES) {
            float s = g_dinv[r0 + 1];
            *(uint2*)(outh + (size_t)(r0 + 1) * 64 + tx * 4) =
                make_uint2(packh(hi0 * s, hi1 * s), packh(hi2 * s, hi3 * s));
        }
    }
}

// ---------------- K1: convert + degree count, 2 edges/thread ---------------
__global__ void k_convert_count(const void* __restrict__ ei) {
    __shared__ int s_nz;
    const int tid = threadIdx.x;
    if (tid == 0) s_nz = 0;
    __syncthreads();
    if (tid < 128 && ((const int*)ei)[2 * tid + 1] != 0) atomicAdd(&s_nz, 1);
    __syncthreads();
    const bool is64 = (s_nz == 0);
    if (blockIdx.x == 0 && tid < SCAN_BLKS) g_bsum[tid] = 0;
    int p = blockIdx.x * 256 + tid;
    int i = p * 2;
    if (i < N_EDGES) {
        int s0, s1, d0, d1;
        if (is64) {
            longlong2 sp = ((const longlong2*)ei)[p];
            longlong2 dp = ((const longlong2*)((const long long*)ei + N_EDGES))[p];
            s0 = (int)sp.x; s1 = (int)sp.y;
            d0 = (int)dp.x; d1 = (int)dp.y;
        } else {
            int2 sp = ((const int2*)ei)[p];
            int2 dp = ((const int2*)((const int*)ei + N_EDGES))[p];
            s0 = sp.x; s1 = sp.y;
            d0 = dp.x; d1 = dp.y;
        }
        if ((unsigned)s0 >= N_NODES) s0 = 0;
        if ((unsigned)s1 >= N_NODES) s1 = 0;
        if ((unsigned)d0 >= N_NODES) d0 = 0;
        if ((unsigned)d1 >= N_NODES) d1 = 0;
        *(int2*)&g_src[i] = make_int2(s0, s1);
        *(int2*)&g_dst[i] = make_int2(d0, d1);
        atomicAdd(&g_cnt[d0], 1);
        atomicAdd(&g_cnt[d1], 1);
    }
}

// ---------------- K2: single-kernel decoupled-lookback scan ----------------
__global__ void k_scan() {
    cudaGridDependencySynchronize();     // needs final g_cnt
    const int b = blockIdx.x, tid = threadIdx.x;
    const int i = b * 256 + tid;
    int v = (i < N_NODES) ? g_cnt[i] : 0;
    const int lane = tid & 31, w = tid >> 5;
    __shared__ int wsum[8];
    __shared__ int s_total, s_prefix;

    int s = v;
    #pragma unroll
    for (int off = 1; off < 32; off <<= 1) {
        int n = __shfl_up_sync(0xffffffffu, s, off);
        if (lane >= off) s += n;
    }
    if (lane == 31) wsum[w] = s;
    __syncthreads();
    if (tid == 0) {
        int acc = 0;
        #pragma unroll
        for (int j = 0; j < 8; j++) { int t = wsum[j]; wsum[j] = acc; acc += t; }
        s_total = acc;
    }
    __syncthreads();
    int incl = wsum[w] + s;

    if (tid == 0) atomicExch(&g_bsum[b], s_total + 1);
    if (tid < 32) {
        int part = 0;
        for (int j = tid; j < b; j += 32) {
            int val;
            do { val = *(volatile int*)&g_bsum[j]; } while (val == 0);
            part += val - 1;
        }
        #pragma unroll
        for (int off = 16; off; off >>= 1)
            part += __shfl_down_sync(0xffffffffu, part, off);
        if (tid == 0) s_prefix = part;
    }
    __syncthreads();

    if (i < N_NODES) {
        g_rowptr[i + 1] = s_prefix + incl;
        g_dinv[i] = rsqrtf((float)(v + 1));
    }
    if (i == 0) g_rowptr[0] = 0;
}

// ---------------- K3: fused [GEMM1(*dinv) | CSR fill] ----------------------
__global__ void k3_fused(const float* __restrict__ x,
                         const float* __restrict__ W1) {
    if (blockIdx.x < GEMM_BLKS) {
        __shared__ float At[32][132];
        __shared__ float Ws[32][68];
        gemm_body<IN_C>(x, W1, g_h1, At, Ws, blockIdx.x * 128);  // syncs inside
    } else {
        cudaGridDependencySynchronize();   // needs g_rowptr (scan)
        int i = (blockIdx.x - GEMM_BLKS) * 256 + threadIdx.x;
        if (i < N_EDGES) {
            int d = g_dst[i];
            int r = atomicSub(&g_cnt[d], 1);   // drains g_cnt back to 0
            int pos = g_rowptr[d] + r - 1;
            if ((unsigned)pos < N_EDGES) g_col[pos] = g_src[i];
        }
    }
}

// ---------------- K4: fused [aggregate L1 + bias + ReLU + GEMM2*dinv] ------
// R12-exact shape: 64 nodes/block, static warp rounds. PDL: W2 staging is
// preamble (input-only), gridDepSync before first g_h1/g_col read.
__global__ void k4_agg_gemm(const float* __restrict__ b1,
                            const float* __restrict__ W2) {
    __shared__ float z1t[64][68];   // [k][row], fp32, pad 68
    __shared__ float Ws[64][68];    // [k][col], fp32

    const int tid   = threadIdx.x;
    const int node0 = blockIdx.x * 64;
    const int lane  = tid & 31;
    const int w     = tid >> 5;

    // preamble: stage W2 (64x64) — input-only, runs before dependency sync
    #pragma unroll
    for (int l = 0; l < 4; l++) {
        int j  = tid + l * 256;
        int k  = j >> 4;
        int c4 = (j & 15) << 2;
        *(float4*)&Ws[k][c4] = *(const float4*)(W2 + (size_t)k * 64 + c4);
    }

    cudaGridDependencySynchronize();     // needs g_h1, g_rowptr, g_col, g_dinv

    // Phase A: aggregate 64 nodes (warp-per-node, 8 rounds)
    const __half2* h2 = (const __half2*)g_h1 + lane;
    float2 bb = ((const float2*)b1)[lane];
    #pragma unroll 1
    for (int round = 0; round < 8; round++) {
        int r  = round * 8 + w;         // 0..63
        int gw = node0 + r;
        float2 v = make_float2(0.0f, 0.0f);
        if (gw < N_NODES) {
            float2 acc = gather_node(h2, gw, lane);
            float dvd = g_dinv[gw];
            v.x = fmaxf(fmaf(acc.x, dvd, bb.x), 0.0f);
            v.y = fmaxf(fmaf(acc.y, dvd, bb.y), 0.0f);
        }
        z1t[2 * lane + 0][r] = v.x;     // transposed store
        z1t[2 * lane + 1][r] = v.y;
    }
    __syncthreads();

    // Phase B: GEMM 64x64x64 from smem, FFMA2 row-pairs
    const int tx = tid & 15;            // 4 cols
    const int ty = tid >> 4;            // 4 rows (2 pairs)
    unsigned long long acc[2][4];
    #pragma unroll
    for (int p = 0; p < 2; p++)
        #pragma unroll
        for (int c = 0; c < 4; c++) acc[p][c] = 0ULL;

    #pragma unroll 8
    for (int k = 0; k < 64; k++) {
        ulonglong2 a = *(const ulonglong2*)&z1t[k][ty * 4];
        float4 b = *(const float4*)&Ws[k][tx * 4];
        unsigned long long B0, B1, B2, B3;
        PACK2(B0, b.x); PACK2(B1, b.y); PACK2(B2, b.z); PACK2(B3, b.w);
        FMA2(acc[0][0], a.x, B0, acc[0][0]);
        FMA2(acc[0][1], a.x, B1, acc[0][1]);
        FMA2(acc[0][2], a.x, B2, acc[0][2]);
        FMA2(acc[0][3], a.x, B3, acc[0][3]);
        FMA2(acc[1][0], a.y, B0, acc[1][0]);
        FMA2(acc[1][1], a.y, B1, acc[1][1]);
        FMA2(acc[1][2], a.y, B2, acc[1][2]);
        FMA2(acc[1][3], a.y, B3, acc[1][3]);
    }

    #pragma unroll
    for (int p = 0; p < 2; p++) {
        float lo0, hi0, lo1, hi1, lo2, hi2, lo3, hi3;
        UNPACK2(lo0, hi0, acc[p][0]);
        UNPACK2(lo1, hi1, acc[p][1]);
        UNPACK2(lo2, hi2, acc[p][2]);
        UNPACK2(lo3, hi3, acc[p][3]);
        int r0 = node0 + ty * 4 + p * 2;
        if (r0 < N_NODES) {
            float s = g_dinv[r0];
            *(uint2*)(g_h2 + (size_t)r0 * 64 + tx * 4) =
                make_uint2(packh(lo0 * s, lo1 * s), packh(lo2 * s, lo3 * s));
        }
        if (r0 + 1 < N_NODES) {
            float s = g_dinv[r0 + 1];
            *(uint2*)(g_h2 + (size_t)(r0 + 1) * 64 + tx * 4) =
                make_uint2(packh(hi0 * s, hi1 * s), packh(hi2 * s, hi3 * s));
        }
    }
}

// ---------------- K5: final aggregation (layer 2) ---------------------------
__global__ void k_aggregate2(const float* __restrict__ bias,
                             float* __restrict__ outp) {
    cudaGridDependencySynchronize();     // needs g_h2
    int gw   = (blockIdx.x * blockDim.x + threadIdx.x) >> 5;
    int lane = threadIdx.x & 31;
    if (gw >= N_NODES) return;

    const __half2* h2 = (const __half2*)g_h2 + lane;
    float2 acc = gather_node(h2, gw, lane);

    float  dvd = g_dinv[gw];
    float2 bb  = ((const float2*)bias)[lane];
    float ox = fmaf(acc.x, dvd, bb.x);
    float oy = fmaf(acc.y, dvd, bb.y);
    ((float2*)outp)[(size_t)gw * 32 + lane] = make_float2(ox, oy);
}

// ---------------- launch (PDL on every boundary after K1) -------------------
template <typename... Args>
static void launch_pdl(void (*kern)(Args...), int grid, int block, Args... args) {
    cudaLaunchConfig_t cfg = {};
    cfg.gridDim  = dim3(grid, 1, 1);
    cfg.blockDim = dim3(block, 1, 1);
    cudaLaunchAttribute attr[1];
    attr[0].id = cudaLaunchAttributeProgrammaticStreamSerialization;
    attr[0].val.programmaticStreamSerializationAllowed = 1;
    cfg.attrs = attr;
    cfg.numAttrs = 1;
    cudaLaunchKernelEx(&cfg, kern, args...);
}

extern "C" void kernel_launch(void* const* d_in, const int* in_sizes, int n_in,
                              void* d_out, int out_size) {
    const float* x  = (const float*)d_in[0];
    const void*  ei = d_in[1];                 // int32 OR int64 [2, 800000]
    const float* W1 = (const float*)d_in[2];
    const float* b1 = (const float*)d_in[3];
    const float* W2 = (const float*)d_in[4];
    const float* b2 = (const float*)d_in[5];
    float*      out = (float*)d_out;

    const int TB = 256;
    const int aggBlocks = (N_NODES * 32 + TB - 1) / TB;   // 6250

    k_convert_count<<<CONV_BLKS, TB>>>(ei);               // edges -> src/dst/cnt
    launch_pdl(k_scan, SCAN_BLKS, TB);                    // rowptr + dinv
    launch_pdl(k3_fused, GEMM_BLKS + EDGE_BLKS, TB,
               (const float*)x, (const float*)W1);        // GEMM1*dinv || CSR fill
    launch_pdl(k4_agg_gemm, K4_BLKS, TB,
               (const float*)b1, (const float*)W2);       // agg1+ReLU+GEMM2 -> g_h2
    launch_pdl(k_aggregate2, aggBlocks, TB,
               (const float*)b2, (float*)out);            // -> out
}